// round 7
// baseline (speedup 1.0000x reference)
#include <cuda_runtime.h>

#define N_NODES 50000
#define N_EDGES_MAX 800000
#define IN_C   128
#define HID_C  128
#define OUT_C  64
#define CAP    128          // neighbor bucket capacity (Poisson mean 16 -> safe)

// ---------------------------------------------------------------------------
// Device-global scratch (no allocations allowed)
// ---------------------------------------------------------------------------
__device__ int   g_cnt [N_NODES];             // per-node neighbor count
__device__ int   g_adj [N_NODES * CAP];       // bucketed adjacency (src ids)
__device__ float g_mean[N_NODES * IN_C];      // mean of neighbor x
__device__ float g_h   [N_NODES * HID_C];     // layer-1 activations
__device__ float g_t   [N_NODES * OUT_C];     // h @ W2_l

// ---------------------------------------------------------------------------
__global__ void k_zero() {
    int i = blockIdx.x * blockDim.x + threadIdx.x;
    if (i < N_NODES) g_cnt[i] = 0;
}

__global__ void k_fill(const int* __restrict__ ei, int E) {
    int e = blockIdx.x * blockDim.x + threadIdx.x;
    if (e >= E) return;
    int s = ei[e];
    int d = ei[E + e];
    int pos = atomicAdd(&g_cnt[d], 1);
    if (pos < CAP) g_adj[d * CAP + pos] = s;
}

// ---------------------------------------------------------------------------
// Aggregation 1 (unchanged)
// ---------------------------------------------------------------------------
__global__ void k_agg1(const float* __restrict__ x) {
    int node = blockIdx.x * (blockDim.x >> 5) + (threadIdx.x >> 5);
    int lane = threadIdx.x & 31;
    if (node >= N_NODES) return;

    int deg = min(g_cnt[node], CAP);
    const int* adj = g_adj + node * CAP;

    float4 a0 = make_float4(0.f, 0.f, 0.f, 0.f);
    float4 a1 = make_float4(0.f, 0.f, 0.f, 0.f);
    float4 a2 = make_float4(0.f, 0.f, 0.f, 0.f);
    float4 a3 = make_float4(0.f, 0.f, 0.f, 0.f);

    int p = 0;
    for (; p + 8 <= deg; p += 8) {
        int4 i0 = *(const int4*)(adj + p);
        int4 i1 = *(const int4*)(adj + p + 4);
        float4 v0 = ((const float4*)(x + (size_t)i0.x * IN_C))[lane];
        float4 v1 = ((const float4*)(x + (size_t)i0.y * IN_C))[lane];
        float4 v2 = ((const float4*)(x + (size_t)i0.z * IN_C))[lane];
        float4 v3 = ((const float4*)(x + (size_t)i0.w * IN_C))[lane];
        float4 v4 = ((const float4*)(x + (size_t)i1.x * IN_C))[lane];
        float4 v5 = ((const float4*)(x + (size_t)i1.y * IN_C))[lane];
        float4 v6 = ((const float4*)(x + (size_t)i1.z * IN_C))[lane];
        float4 v7 = ((const float4*)(x + (size_t)i1.w * IN_C))[lane];
        a0.x += v0.x; a0.y += v0.y; a0.z += v0.z; a0.w += v0.w;
        a1.x += v1.x; a1.y += v1.y; a1.z += v1.z; a1.w += v1.w;
        a2.x += v2.x; a2.y += v2.y; a2.z += v2.z; a2.w += v2.w;
        a3.x += v3.x; a3.y += v3.y; a3.z += v3.z; a3.w += v3.w;
        a0.x += v4.x; a0.y += v4.y; a0.z += v4.z; a0.w += v4.w;
        a1.x += v5.x; a1.y += v5.y; a1.z += v5.z; a1.w += v5.w;
        a2.x += v6.x; a2.y += v6.y; a2.z += v6.z; a2.w += v6.w;
        a3.x += v7.x; a3.y += v7.y; a3.z += v7.z; a3.w += v7.w;
    }
    if (p + 4 <= deg) {
        int4 i0 = *(const int4*)(adj + p);
        float4 v0 = ((const float4*)(x + (size_t)i0.x * IN_C))[lane];
        float4 v1 = ((const float4*)(x + (size_t)i0.y * IN_C))[lane];
        float4 v2 = ((const float4*)(x + (size_t)i0.z * IN_C))[lane];
        float4 v3 = ((const float4*)(x + (size_t)i0.w * IN_C))[lane];
        a0.x += v0.x; a0.y += v0.y; a0.z += v0.z; a0.w += v0.w;
        a1.x += v1.x; a1.y += v1.y; a1.z += v1.z; a1.w += v1.w;
        a2.x += v2.x; a2.y += v2.y; a2.z += v2.z; a2.w += v2.w;
        a3.x += v3.x; a3.y += v3.y; a3.z += v3.z; a3.w += v3.w;
        p += 4;
    }
    for (; p < deg; p++) {
        int s = adj[p];
        float4 v = ((const float4*)(x + (size_t)s * IN_C))[lane];
        a0.x += v.x; a0.y += v.y; a0.z += v.z; a0.w += v.w;
    }
    float4 acc;
    acc.x = (a0.x + a1.x) + (a2.x + a3.x);
    acc.y = (a0.y + a1.y) + (a2.y + a3.y);
    acc.z = (a0.z + a1.z) + (a2.z + a3.z);
    acc.w = (a0.w + a1.w) + (a2.w + a3.w);
    float inv = (deg > 0) ? 1.f / (float)deg : 0.f;
    acc.x *= inv; acc.y *= inv; acc.z *= inv; acc.w *= inv;
    ((float4*)(g_mean + (size_t)node * IN_C))[lane] = acc;
}

// ---------------------------------------------------------------------------
// TF32 / MMA helpers
// ---------------------------------------------------------------------------
__device__ __forceinline__ unsigned f2tf32(float f) {
    unsigned u;
    asm("cvt.rna.tf32.f32 %0, %1;" : "=r"(u) : "f"(f));
    return u;
}

__device__ __forceinline__ void mma_tf32(float d[4], const unsigned a[4],
                                         const unsigned b[2]) {
    asm volatile(
        "mma.sync.aligned.m16n8k8.row.col.f32.tf32.tf32.f32 "
        "{%0,%1,%2,%3}, {%4,%5,%6,%7}, {%8,%9}, {%0,%1,%2,%3};"
        : "+f"(d[0]), "+f"(d[1]), "+f"(d[2]), "+f"(d[3])
        : "r"(a[0]), "r"(a[1]), "r"(a[2]), "r"(a[3]), "r"(b[0]), "r"(b[1]));
}

// ldmatrix.x4: four 8x8 b16 tiles == four 8x4 tf32 tiles; lane->(row,colpair)
// mapping matches the m16n8k8 tf32 fragment layout exactly.
__device__ __forceinline__ void ldsm_x4(unsigned r[4], unsigned addr) {
    asm volatile(
        "ldmatrix.sync.aligned.m8n8.x4.shared.b16 {%0,%1,%2,%3}, [%4];"
        : "=r"(r[0]), "=r"(r[1]), "=r"(r[2]), "=r"(r[3])
        : "r"(addr));
}

// ---------------------------------------------------------------------------
// GEMM 1 (TF32 + LDSM): h = relu( [mean | x] @ [W1_l ; W1_r] + b1 )
// Block 128x128, BK=16, double-buffered, 8 warps 2x4, warp tile 64x32.
// ---------------------------------------------------------------------------
__global__ __launch_bounds__(256) void k_gemm1(const float* __restrict__ x,
                                               const float* __restrict__ W1l,
                                               const float* __restrict__ b1,
                                               const float* __restrict__ W1r) {
    __shared__ unsigned As[2][128][20];   // [buf][m][k]
    __shared__ unsigned Bs[2][128][20];   // [buf][n][k]

    const int tid  = threadIdx.x;
    const int brow = blockIdx.x * 128;

    const int arow = tid >> 1;
    const int akb  = (tid & 1) * 8;
    const int ra   = min(brow + arow, N_NODES - 1);
    const int bk = tid >> 4;
    const int bn = (tid & 15) * 8;

    const int wid  = tid >> 5;
    const int lane = tid & 31;
    const int g    = lane >> 2;
    const int t    = lane & 3;
    const int m0   = (wid >> 2) * 64;
    const int n0   = (wid & 3) * 32;
    const int lrow = lane & 15;          // ldmatrix row within 16-row group
    const int lkof = (lane >> 4) * 4;    // ldmatrix k-chunk selector

    float acc[4][4][4];
#pragma unroll
    for (int mt = 0; mt < 4; mt++)
#pragma unroll
        for (int nt = 0; nt < 4; nt++)
#pragma unroll
            for (int r = 0; r < 4; r++) acc[mt][nt][r] = 0.f;

    float4 pa0, pa1, pb0, pb1;

    auto loadG = [&](int kc) {
        int kg = kc + akb;
        const float* srcA = (kg < 128) ? (g_mean + (size_t)ra * 128 + kg)
                                       : (x + (size_t)ra * 128 + (kg - 128));
        pa0 = *(const float4*)(srcA);
        pa1 = *(const float4*)(srcA + 4);
        int kgb = kc + bk;
        const float* srcB = (kgb < 128) ? (W1l + (size_t)kgb * 128 + bn)
                                        : (W1r + (size_t)(kgb - 128) * 128 + bn);
        pb0 = *(const float4*)(srcB);
        pb1 = *(const float4*)(srcB + 4);
    };
    auto storeS = [&](int buf) {
        uint4 u0 = make_uint4(f2tf32(pa0.x), f2tf32(pa0.y), f2tf32(pa0.z), f2tf32(pa0.w));
        uint4 u1 = make_uint4(f2tf32(pa1.x), f2tf32(pa1.y), f2tf32(pa1.z), f2tf32(pa1.w));
        *(uint4*)&As[buf][arow][akb]     = u0;
        *(uint4*)&As[buf][arow][akb + 4] = u1;
        Bs[buf][bn + 0][bk] = f2tf32(pb0.x);
        Bs[buf][bn + 1][bk] = f2tf32(pb0.y);
        Bs[buf][bn + 2][bk] = f2tf32(pb0.z);
        Bs[buf][bn + 3][bk] = f2tf32(pb0.w);
        Bs[buf][bn + 4][bk] = f2tf32(pb1.x);
        Bs[buf][bn + 5][bk] = f2tf32(pb1.y);
        Bs[buf][bn + 6][bk] = f2tf32(pb1.z);
        Bs[buf][bn + 7][bk] = f2tf32(pb1.w);
    };

    loadG(0);
    storeS(0);
    __syncthreads();

    int buf = 0;
    for (int kc = 0; kc < 256; kc += 16) {
        bool has_next = (kc + 16) < 256;
        if (has_next) loadG(kc + 16);

#pragma unroll
        for (int kk = 0; kk < 16; kk += 8) {
            unsigned afr[4][4];
#pragma unroll
            for (int mt = 0; mt < 4; mt++) {
                unsigned addr = (unsigned)__cvta_generic_to_shared(
                    &As[buf][m0 + mt * 16 + lrow][kk + lkof]);
                ldsm_x4(afr[mt], addr);
            }
            unsigned bfr[4][2];
            {
                unsigned r[4];
                unsigned addr0 = (unsigned)__cvta_generic_to_shared(
                    &Bs[buf][n0 + lrow][kk + lkof]);
                ldsm_x4(r, addr0);
                bfr[0][0] = r[0]; bfr[1][0] = r[1];
                bfr[0][1] = r[2]; bfr[1][1] = r[3];
                unsigned addr1 = (unsigned)__cvta_generic_to_shared(
                    &Bs[buf][n0 + 16 + lrow][kk + lkof]);
                ldsm_x4(r, addr1);
                bfr[2][0] = r[0]; bfr[3][0] = r[1];
                bfr[2][1] = r[2]; bfr[3][1] = r[3];
            }
#pragma unroll
            for (int mt = 0; mt < 4; mt++)
#pragma unroll
                for (int nt = 0; nt < 4; nt++)
                    mma_tf32(acc[mt][nt], afr[mt], bfr[nt]);
        }

        if (has_next) {
            storeS(buf ^ 1);
            __syncthreads();
            buf ^= 1;
        }
    }

#pragma unroll
    for (int nt = 0; nt < 4; nt++) {
        int c = n0 + nt * 8 + 2 * t;
        float2 bb = *(const float2*)(b1 + c);
#pragma unroll
        for (int mt = 0; mt < 4; mt++) {
            int r0 = brow + m0 + mt * 16 + g;
            if (r0 < N_NODES) {
                float2 o;
                o.x = fmaxf(acc[mt][nt][0] + bb.x, 0.f);
                o.y = fmaxf(acc[mt][nt][1] + bb.y, 0.f);
                *(float2*)(g_h + (size_t)r0 * 128 + c) = o;
            }
            int r1 = r0 + 8;
            if (r1 < N_NODES) {
                float2 o;
                o.x = fmaxf(acc[mt][nt][2] + bb.x, 0.f);
                o.y = fmaxf(acc[mt][nt][3] + bb.y, 0.f);
                *(float2*)(g_h + (size_t)r1 * 128 + c) = o;
            }
        }
    }
}

// ---------------------------------------------------------------------------
// GEMM 2 (TF32 + LDSM): t = h @ W2_l ; out = h @ W2_r + b2
// ---------------------------------------------------------------------------
__global__ __launch_bounds__(256) void k_gemm2(const float* __restrict__ W2l,
                                               const float* __restrict__ b2,
                                               const float* __restrict__ W2r,
                                               float* __restrict__ out) {
    __shared__ unsigned As[2][128][20];
    __shared__ unsigned Bs[2][128][20];

    const int tid  = threadIdx.x;
    const int brow = blockIdx.x * 128;

    const int arow = tid >> 1;
    const int akb  = (tid & 1) * 8;
    const int ra   = min(brow + arow, N_NODES - 1);
    const int bk = tid >> 4;
    const int bn = (tid & 15) * 8;

    const int wid  = tid >> 5;
    const int lane = tid & 31;
    const int g    = lane >> 2;
    const int t    = lane & 3;
    const int m0   = (wid >> 2) * 64;
    const int n0   = (wid & 3) * 32;
    const int lrow = lane & 15;
    const int lkof = (lane >> 4) * 4;

    float acc[4][4][4];
#pragma unroll
    for (int mt = 0; mt < 4; mt++)
#pragma unroll
        for (int nt = 0; nt < 4; nt++)
#pragma unroll
            for (int r = 0; r < 4; r++) acc[mt][nt][r] = 0.f;

    float4 pa0, pa1, pb0, pb1;

    auto loadG = [&](int kc) {
        const float* srcA = g_h + (size_t)ra * 128 + kc + akb;
        pa0 = *(const float4*)(srcA);
        pa1 = *(const float4*)(srcA + 4);
        int kg = kc + bk;
        const float* srcB = (bn < 64) ? (W2l + (size_t)kg * 64 + bn)
                                      : (W2r + (size_t)kg * 64 + (bn - 64));
        pb0 = *(const float4*)(srcB);
        pb1 = *(const float4*)(srcB + 4);
    };
    auto storeS = [&](int buf) {
        uint4 u0 = make_uint4(f2tf32(pa0.x), f2tf32(pa0.y), f2tf32(pa0.z), f2tf32(pa0.w));
        uint4 u1 = make_uint4(f2tf32(pa1.x), f2tf32(pa1.y), f2tf32(pa1.z), f2tf32(pa1.w));
        *(uint4*)&As[buf][arow][akb]     = u0;
        *(uint4*)&As[buf][arow][akb + 4] = u1;
        Bs[buf][bn + 0][bk] = f2tf32(pb0.x);
        Bs[buf][bn + 1][bk] = f2tf32(pb0.y);
        Bs[buf][bn + 2][bk] = f2tf32(pb0.z);
        Bs[buf][bn + 3][bk] = f2tf32(pb0.w);
        Bs[buf][bn + 4][bk] = f2tf32(pb1.x);
        Bs[buf][bn + 5][bk] = f2tf32(pb1.y);
        Bs[buf][bn + 6][bk] = f2tf32(pb1.z);
        Bs[buf][bn + 7][bk] = f2tf32(pb1.w);
    };

    loadG(0);
    storeS(0);
    __syncthreads();

    int buf = 0;
    for (int kc = 0; kc < 128; kc += 16) {
        bool has_next = (kc + 16) < 128;
        if (has_next) loadG(kc + 16);

#pragma unroll
        for (int kk = 0; kk < 16; kk += 8) {
            unsigned afr[4][4];
#pragma unroll
            for (int mt = 0; mt < 4; mt++) {
                unsigned addr = (unsigned)__cvta_generic_to_shared(
                    &As[buf][m0 + mt * 16 + lrow][kk + lkof]);
                ldsm_x4(afr[mt], addr);
            }
            unsigned bfr[4][2];
            {
                unsigned r[4];
                unsigned addr0 = (unsigned)__cvta_generic_to_shared(
                    &Bs[buf][n0 + lrow][kk + lkof]);
                ldsm_x4(r, addr0);
                bfr[0][0] = r[0]; bfr[1][0] = r[1];
                bfr[0][1] = r[2]; bfr[1][1] = r[3];
                unsigned addr1 = (unsigned)__cvta_generic_to_shared(
                    &Bs[buf][n0 + 16 + lrow][kk + lkof]);
                ldsm_x4(r, addr1);
                bfr[2][0] = r[0]; bfr[3][0] = r[1];
                bfr[2][1] = r[2]; bfr[3][1] = r[3];
            }
#pragma unroll
            for (int mt = 0; mt < 4; mt++)
#pragma unroll
                for (int nt = 0; nt < 4; nt++)
                    mma_tf32(acc[mt][nt], afr[mt], bfr[nt]);
        }

        if (has_next) {
            storeS(buf ^ 1);
            __syncthreads();
            buf ^= 1;
        }
    }

#pragma unroll
    for (int nt = 0; nt < 4; nt++) {
        int c = n0 + nt * 8 + 2 * t;
        if (c < 64) {
#pragma unroll
            for (int mt = 0; mt < 4; mt++) {
                int r0 = brow + m0 + mt * 16 + g;
                if (r0 < N_NODES)
                    *(float2*)(g_t + (size_t)r0 * 64 + c) =
                        make_float2(acc[mt][nt][0], acc[mt][nt][1]);
                int r1 = r0 + 8;
                if (r1 < N_NODES)
                    *(float2*)(g_t + (size_t)r1 * 64 + c) =
                        make_float2(acc[mt][nt][2], acc[mt][nt][3]);
            }
        } else {
            int co = c - 64;
            float2 bb = *(const float2*)(b2 + co);
#pragma unroll
            for (int mt = 0; mt < 4; mt++) {
                int r0 = brow + m0 + mt * 16 + g;
                if (r0 < N_NODES)
                    *(float2*)(out + (size_t)r0 * 64 + co) =
                        make_float2(acc[mt][nt][0] + bb.x, acc[mt][nt][1] + bb.y);
                int r1 = r0 + 8;
                if (r1 < N_NODES)
                    *(float2*)(out + (size_t)r1 * 64 + co) =
                        make_float2(acc[mt][nt][2] + bb.x, acc[mt][nt][3] + bb.y);
            }
        }
    }
}

// ---------------------------------------------------------------------------
// Aggregation 2 + final (unchanged)
// ---------------------------------------------------------------------------
__global__ void k_agg2(float* __restrict__ out) {
    int node = blockIdx.x * (blockDim.x >> 5) + (threadIdx.x >> 5);
    int lane = threadIdx.x & 31;
    if (node >= N_NODES) return;

    int deg = min(g_cnt[node], CAP);
    const int* adj = g_adj + node * CAP;

    float2 a0 = make_float2(0.f, 0.f);
    float2 a1 = make_float2(0.f, 0.f);
    float2 a2 = make_float2(0.f, 0.f);
    float2 a3 = make_float2(0.f, 0.f);

    int p = 0;
    for (; p + 8 <= deg; p += 8) {
        int4 i0 = *(const int4*)(adj + p);
        int4 i1 = *(const int4*)(adj + p + 4);
        float2 v0 = ((const float2*)(g_t + (size_t)i0.x * OUT_C))[lane];
        float2 v1 = ((const float2*)(g_t + (size_t)i0.y * OUT_C))[lane];
        float2 v2 = ((const float2*)(g_t + (size_t)i0.z * OUT_C))[lane];
        float2 v3 = ((const float2*)(g_t + (size_t)i0.w * OUT_C))[lane];
        float2 v4 = ((const float2*)(g_t + (size_t)i1.x * OUT_C))[lane];
        float2 v5 = ((const float2*)(g_t + (size_t)i1.y * OUT_C))[lane];
        float2 v6 = ((const float2*)(g_t + (size_t)i1.z * OUT_C))[lane];
        float2 v7 = ((const float2*)(g_t + (size_t)i1.w * OUT_C))[lane];
        a0.x += v0.x; a0.y += v0.y;
        a1.x += v1.x; a1.y += v1.y;
        a2.x += v2.x; a2.y += v2.y;
        a3.x += v3.x; a3.y += v3.y;
        a0.x += v4.x; a0.y += v4.y;
        a1.x += v5.x; a1.y += v5.y;
        a2.x += v6.x; a2.y += v6.y;
        a3.x += v7.x; a3.y += v7.y;
    }
    if (p + 4 <= deg) {
        int4 i0 = *(const int4*)(adj + p);
        float2 v0 = ((const float2*)(g_t + (size_t)i0.x * OUT_C))[lane];
        float2 v1 = ((const float2*)(g_t + (size_t)i0.y * OUT_C))[lane];
        float2 v2 = ((const float2*)(g_t + (size_t)i0.z * OUT_C))[lane];
        float2 v3 = ((const float2*)(g_t + (size_t)i0.w * OUT_C))[lane];
        a0.x += v0.x; a0.y += v0.y;
        a1.x += v1.x; a1.y += v1.y;
        a2.x += v2.x; a2.y += v2.y;
        a3.x += v3.x; a3.y += v3.y;
        p += 4;
    }
    for (; p < deg; p++) {
        int s = adj[p];
        float2 v = ((const float2*)(g_t + (size_t)s * OUT_C))[lane];
        a0.x += v.x; a0.y += v.y;
    }
    float inv = (deg > 0) ? 1.f / (float)deg : 0.f;
    float sx = ((a0.x + a1.x) + (a2.x + a3.x)) * inv;
    float sy = ((a0.y + a1.y) + (a2.y + a3.y)) * inv;

    float2* o = (float2*)(out + (size_t)node * OUT_C) + lane;
    float2 cur = *o;
    cur.x += sx;
    cur.y += sy;
    *o = cur;
}

// ---------------------------------------------------------------------------
extern "C" void kernel_launch(void* const* d_in, const int* in_sizes, int n_in,
                              void* d_out, int out_size) {
    const float* x   = (const float*)d_in[0];
    const int*   ei  = (const int*)d_in[1];     // int32 (JAX default x64 off)
    const float* W1l = (const float*)d_in[2];
    const float* b1  = (const float*)d_in[3];
    const float* W1r = (const float*)d_in[4];
    const float* W2l = (const float*)d_in[5];
    const float* b2  = (const float*)d_in[6];
    const float* W2r = (const float*)d_in[7];
    float* out = (float*)d_out;

    const int E = in_sizes[1] / 2;

    k_zero<<<(N_NODES + 255) / 256, 256>>>();
    k_fill<<<(E + 255) / 256, 256>>>(ei, E);

    k_agg1<<<(N_NODES + 7) / 8, 256>>>(x);
    k_gemm1<<<(N_NODES + 127) / 128, 256>>>(x, W1l, b1, W1r);

    k_gemm2<<<(N_NODES + 127) / 128, 256>>>(W2l, b2, W2r, out);
    k_agg2<<<(N_NODES + 7) / 8, 256>>>(out);
}

// round 8
// speedup vs baseline: 1.1645x; 1.1645x over previous
#include <cuda_runtime.h>

#define N_NODES 50000
#define N_EDGES_MAX 800000
#define IN_C   128
#define HID_C  128
#define OUT_C  64
#define CAP    128          // neighbor bucket capacity (Poisson mean 16 -> safe)

// ---------------------------------------------------------------------------
// Device-global scratch (no allocations allowed)
// ---------------------------------------------------------------------------
__device__ int   g_cnt [N_NODES];             // per-node neighbor count
__device__ int   g_adj [N_NODES * CAP];       // bucketed adjacency (src ids)
__device__ float g_mean[N_NODES * IN_C];      // mean of neighbor x
__device__ float g_h   [N_NODES * HID_C];     // layer-1 activations
__device__ float g_t   [N_NODES * OUT_C];     // h @ W2_l

// ---------------------------------------------------------------------------
__global__ void k_zero() {
    int i = blockIdx.x * blockDim.x + threadIdx.x;
    if (i < N_NODES) g_cnt[i] = 0;
}

__global__ void k_fill(const int* __restrict__ ei, int E) {
    int e = blockIdx.x * blockDim.x + threadIdx.x;
    if (e >= E) return;
    int s = ei[e];
    int d = ei[E + e];
    int pos = atomicAdd(&g_cnt[d], 1);
    if (pos < CAP) g_adj[d * CAP + pos] = s;
}

// ---------------------------------------------------------------------------
// Aggregation 1 (unchanged)
// ---------------------------------------------------------------------------
__global__ void k_agg1(const float* __restrict__ x) {
    int node = blockIdx.x * (blockDim.x >> 5) + (threadIdx.x >> 5);
    int lane = threadIdx.x & 31;
    if (node >= N_NODES) return;

    int deg = min(g_cnt[node], CAP);
    const int* adj = g_adj + node * CAP;

    float4 a0 = make_float4(0.f, 0.f, 0.f, 0.f);
    float4 a1 = make_float4(0.f, 0.f, 0.f, 0.f);
    float4 a2 = make_float4(0.f, 0.f, 0.f, 0.f);
    float4 a3 = make_float4(0.f, 0.f, 0.f, 0.f);

    int p = 0;
    for (; p + 8 <= deg; p += 8) {
        int4 i0 = *(const int4*)(adj + p);
        int4 i1 = *(const int4*)(adj + p + 4);
        float4 v0 = ((const float4*)(x + (size_t)i0.x * IN_C))[lane];
        float4 v1 = ((const float4*)(x + (size_t)i0.y * IN_C))[lane];
        float4 v2 = ((const float4*)(x + (size_t)i0.z * IN_C))[lane];
        float4 v3 = ((const float4*)(x + (size_t)i0.w * IN_C))[lane];
        float4 v4 = ((const float4*)(x + (size_t)i1.x * IN_C))[lane];
        float4 v5 = ((const float4*)(x + (size_t)i1.y * IN_C))[lane];
        float4 v6 = ((const float4*)(x + (size_t)i1.z * IN_C))[lane];
        float4 v7 = ((const float4*)(x + (size_t)i1.w * IN_C))[lane];
        a0.x += v0.x; a0.y += v0.y; a0.z += v0.z; a0.w += v0.w;
        a1.x += v1.x; a1.y += v1.y; a1.z += v1.z; a1.w += v1.w;
        a2.x += v2.x; a2.y += v2.y; a2.z += v2.z; a2.w += v2.w;
        a3.x += v3.x; a3.y += v3.y; a3.z += v3.z; a3.w += v3.w;
        a0.x += v4.x; a0.y += v4.y; a0.z += v4.z; a0.w += v4.w;
        a1.x += v5.x; a1.y += v5.y; a1.z += v5.z; a1.w += v5.w;
        a2.x += v6.x; a2.y += v6.y; a2.z += v6.z; a2.w += v6.w;
        a3.x += v7.x; a3.y += v7.y; a3.z += v7.z; a3.w += v7.w;
    }
    if (p + 4 <= deg) {
        int4 i0 = *(const int4*)(adj + p);
        float4 v0 = ((const float4*)(x + (size_t)i0.x * IN_C))[lane];
        float4 v1 = ((const float4*)(x + (size_t)i0.y * IN_C))[lane];
        float4 v2 = ((const float4*)(x + (size_t)i0.z * IN_C))[lane];
        float4 v3 = ((const float4*)(x + (size_t)i0.w * IN_C))[lane];
        a0.x += v0.x; a0.y += v0.y; a0.z += v0.z; a0.w += v0.w;
        a1.x += v1.x; a1.y += v1.y; a1.z += v1.z; a1.w += v1.w;
        a2.x += v2.x; a2.y += v2.y; a2.z += v2.z; a2.w += v2.w;
        a3.x += v3.x; a3.y += v3.y; a3.z += v3.z; a3.w += v3.w;
        p += 4;
    }
    for (; p < deg; p++) {
        int s = adj[p];
        float4 v = ((const float4*)(x + (size_t)s * IN_C))[lane];
        a0.x += v.x; a0.y += v.y; a0.z += v.z; a0.w += v.w;
    }
    float4 acc;
    acc.x = (a0.x + a1.x) + (a2.x + a3.x);
    acc.y = (a0.y + a1.y) + (a2.y + a3.y);
    acc.z = (a0.z + a1.z) + (a2.z + a3.z);
    acc.w = (a0.w + a1.w) + (a2.w + a3.w);
    float inv = (deg > 0) ? 1.f / (float)deg : 0.f;
    acc.x *= inv; acc.y *= inv; acc.z *= inv; acc.w *= inv;
    ((float4*)(g_mean + (size_t)node * IN_C))[lane] = acc;
}

// ---------------------------------------------------------------------------
// TF32 / MMA helpers
// ---------------------------------------------------------------------------
__device__ __forceinline__ unsigned f2tf32(float f) {
    unsigned u;
    asm("cvt.rna.tf32.f32 %0, %1;" : "=r"(u) : "f"(f));
    return u;
}

__device__ __forceinline__ void mma_tf32(float d[4], const unsigned a[4],
                                         const unsigned b[2]) {
    asm volatile(
        "mma.sync.aligned.m16n8k8.row.col.f32.tf32.tf32.f32 "
        "{%0,%1,%2,%3}, {%4,%5,%6,%7}, {%8,%9}, {%0,%1,%2,%3};"
        : "+f"(d[0]), "+f"(d[1]), "+f"(d[2]), "+f"(d[3])
        : "r"(a[0]), "r"(a[1]), "r"(a[2]), "r"(a[3]), "r"(b[0]), "r"(b[1]));
}

#define SSTR 136   // smem row stride in words: 136 mod 32 = 8 -> conflict-free frag loads

// ---------------------------------------------------------------------------
// GEMM 1 (TF32, k-major smem): h = relu( [mean | x] @ [W1_l ; W1_r] + b1 )
// Block 128x128, BK=16, double-buffered, 8 warps 2x4, warp tile 64x32.
// As[k][m], Bs[k][n]: conflict-free fills AND conflict-free fragment loads.
// ---------------------------------------------------------------------------
__global__ __launch_bounds__(256) void k_gemm1(const float* __restrict__ x,
                                               const float* __restrict__ W1l,
                                               const float* __restrict__ b1,
                                               const float* __restrict__ W1r) {
    __shared__ unsigned As[2][16][SSTR];   // [buf][k][m]
    __shared__ unsigned Bs[2][16][SSTR];   // [buf][k][n]

    const int tid  = threadIdx.x;
    const int brow = blockIdx.x * 128;

    // A fill: thread owns row m = tid&127, k-chunk akb = (tid>>7)*8
    const int am  = tid & 127;
    const int akb = (tid >> 7) * 8;
    const int ra  = min(brow + am, N_NODES - 1);
    // B fill: thread owns k-row bkr = tid>>4, n-chunk bnc = (tid&15)*8
    const int bkr = tid >> 4;
    const int bnc = (tid & 15) * 8;

    const int wid  = tid >> 5;
    const int lane = tid & 31;
    const int g    = lane >> 2;
    const int t    = lane & 3;
    const int m0   = (wid >> 2) * 64;
    const int n0   = (wid & 3) * 32;

    float acc[4][4][4];
#pragma unroll
    for (int mt = 0; mt < 4; mt++)
#pragma unroll
        for (int nt = 0; nt < 4; nt++)
#pragma unroll
            for (int r = 0; r < 4; r++) acc[mt][nt][r] = 0.f;

    float4 pa0, pa1, pb0, pb1;

    auto loadG = [&](int kc) {
        int kg = kc + akb;
        const float* srcA = (kg < 128) ? (g_mean + (size_t)ra * 128 + kg)
                                       : (x + (size_t)ra * 128 + (kg - 128));
        pa0 = *(const float4*)(srcA);
        pa1 = *(const float4*)(srcA + 4);
        int kgb = kc + bkr;
        const float* srcB = (kgb < 128) ? (W1l + (size_t)kgb * 128 + bnc)
                                        : (W1r + (size_t)(kgb - 128) * 128 + bnc);
        pb0 = *(const float4*)(srcB);
        pb1 = *(const float4*)(srcB + 4);
    };
    auto storeS = [&](int buf) {
        As[buf][akb + 0][am] = f2tf32(pa0.x);
        As[buf][akb + 1][am] = f2tf32(pa0.y);
        As[buf][akb + 2][am] = f2tf32(pa0.z);
        As[buf][akb + 3][am] = f2tf32(pa0.w);
        As[buf][akb + 4][am] = f2tf32(pa1.x);
        As[buf][akb + 5][am] = f2tf32(pa1.y);
        As[buf][akb + 6][am] = f2tf32(pa1.z);
        As[buf][akb + 7][am] = f2tf32(pa1.w);
        uint4 u0 = make_uint4(f2tf32(pb0.x), f2tf32(pb0.y), f2tf32(pb0.z), f2tf32(pb0.w));
        uint4 u1 = make_uint4(f2tf32(pb1.x), f2tf32(pb1.y), f2tf32(pb1.z), f2tf32(pb1.w));
        *(uint4*)&Bs[buf][bkr][bnc]     = u0;
        *(uint4*)&Bs[buf][bkr][bnc + 4] = u1;
    };

    loadG(0);
    storeS(0);
    __syncthreads();

    int buf = 0;
    for (int kc = 0; kc < 256; kc += 16) {
        bool has_next = (kc + 16) < 256;
        if (has_next) loadG(kc + 16);

#pragma unroll
        for (int kk = 0; kk < 16; kk += 8) {
            unsigned afr[4][4];
#pragma unroll
            for (int mt = 0; mt < 4; mt++) {
                int mr = m0 + mt * 16 + g;
                afr[mt][0] = As[buf][kk + t][mr];
                afr[mt][1] = As[buf][kk + t][mr + 8];
                afr[mt][2] = As[buf][kk + t + 4][mr];
                afr[mt][3] = As[buf][kk + t + 4][mr + 8];
            }
            unsigned bfr[4][2];
#pragma unroll
            for (int nt = 0; nt < 4; nt++) {
                int nr = n0 + nt * 8 + g;
                bfr[nt][0] = Bs[buf][kk + t][nr];
                bfr[nt][1] = Bs[buf][kk + t + 4][nr];
            }
#pragma unroll
            for (int mt = 0; mt < 4; mt++)
#pragma unroll
                for (int nt = 0; nt < 4; nt++)
                    mma_tf32(acc[mt][nt], afr[mt], bfr[nt]);
        }

        if (has_next) {
            storeS(buf ^ 1);
            __syncthreads();
            buf ^= 1;
        }
    }

#pragma unroll
    for (int nt = 0; nt < 4; nt++) {
        int c = n0 + nt * 8 + 2 * t;
        float2 bb = *(const float2*)(b1 + c);
#pragma unroll
        for (int mt = 0; mt < 4; mt++) {
            int r0 = brow + m0 + mt * 16 + g;
            if (r0 < N_NODES) {
                float2 o;
                o.x = fmaxf(acc[mt][nt][0] + bb.x, 0.f);
                o.y = fmaxf(acc[mt][nt][1] + bb.y, 0.f);
                *(float2*)(g_h + (size_t)r0 * 128 + c) = o;
            }
            int r1 = r0 + 8;
            if (r1 < N_NODES) {
                float2 o;
                o.x = fmaxf(acc[mt][nt][2] + bb.x, 0.f);
                o.y = fmaxf(acc[mt][nt][3] + bb.y, 0.f);
                *(float2*)(g_h + (size_t)r1 * 128 + c) = o;
            }
        }
    }
}

// ---------------------------------------------------------------------------
// GEMM 2 (TF32, k-major smem): t = h @ W2_l ; out = h @ W2_r + b2
// ---------------------------------------------------------------------------
__global__ __launch_bounds__(256) void k_gemm2(const float* __restrict__ W2l,
                                               const float* __restrict__ b2,
                                               const float* __restrict__ W2r,
                                               float* __restrict__ out) {
    __shared__ unsigned As[2][16][SSTR];
    __shared__ unsigned Bs[2][16][SSTR];

    const int tid  = threadIdx.x;
    const int brow = blockIdx.x * 128;

    const int am  = tid & 127;
    const int akb = (tid >> 7) * 8;
    const int ra  = min(brow + am, N_NODES - 1);
    const int bkr = tid >> 4;
    const int bnc = (tid & 15) * 8;

    const int wid  = tid >> 5;
    const int lane = tid & 31;
    const int g    = lane >> 2;
    const int t    = lane & 3;
    const int m0   = (wid >> 2) * 64;
    const int n0   = (wid & 3) * 32;

    float acc[4][4][4];
#pragma unroll
    for (int mt = 0; mt < 4; mt++)
#pragma unroll
        for (int nt = 0; nt < 4; nt++)
#pragma unroll
            for (int r = 0; r < 4; r++) acc[mt][nt][r] = 0.f;

    float4 pa0, pa1, pb0, pb1;

    auto loadG = [&](int kc) {
        const float* srcA = g_h + (size_t)ra * 128 + kc + akb;
        pa0 = *(const float4*)(srcA);
        pa1 = *(const float4*)(srcA + 4);
        int kg = kc + bkr;
        const float* srcB = (bnc < 64) ? (W2l + (size_t)kg * 64 + bnc)
                                       : (W2r + (size_t)kg * 64 + (bnc - 64));
        pb0 = *(const float4*)(srcB);
        pb1 = *(const float4*)(srcB + 4);
    };
    auto storeS = [&](int buf) {
        As[buf][akb + 0][am] = f2tf32(pa0.x);
        As[buf][akb + 1][am] = f2tf32(pa0.y);
        As[buf][akb + 2][am] = f2tf32(pa0.z);
        As[buf][akb + 3][am] = f2tf32(pa0.w);
        As[buf][akb + 4][am] = f2tf32(pa1.x);
        As[buf][akb + 5][am] = f2tf32(pa1.y);
        As[buf][akb + 6][am] = f2tf32(pa1.z);
        As[buf][akb + 7][am] = f2tf32(pa1.w);
        uint4 u0 = make_uint4(f2tf32(pb0.x), f2tf32(pb0.y), f2tf32(pb0.z), f2tf32(pb0.w));
        uint4 u1 = make_uint4(f2tf32(pb1.x), f2tf32(pb1.y), f2tf32(pb1.z), f2tf32(pb1.w));
        *(uint4*)&Bs[buf][bkr][bnc]     = u0;
        *(uint4*)&Bs[buf][bkr][bnc + 4] = u1;
    };

    loadG(0);
    storeS(0);
    __syncthreads();

    int buf = 0;
    for (int kc = 0; kc < 128; kc += 16) {
        bool has_next = (kc + 16) < 128;
        if (has_next) loadG(kc + 16);

#pragma unroll
        for (int kk = 0; kk < 16; kk += 8) {
            unsigned afr[4][4];
#pragma unroll
            for (int mt = 0; mt < 4; mt++) {
                int mr = m0 + mt * 16 + g;
                afr[mt][0] = As[buf][kk + t][mr];
                afr[mt][1] = As[buf][kk + t][mr + 8];
                afr[mt][2] = As[buf][kk + t + 4][mr];
                afr[mt][3] = As[buf][kk + t + 4][mr + 8];
            }
            unsigned bfr[4][2];
#pragma unroll
            for (int nt = 0; nt < 4; nt++) {
                int nr = n0 + nt * 8 + g;
                bfr[nt][0] = Bs[buf][kk + t][nr];
                bfr[nt][1] = Bs[buf][kk + t + 4][nr];
            }
#pragma unroll
            for (int mt = 0; mt < 4; mt++)
#pragma unroll
                for (int nt = 0; nt < 4; nt++)
                    mma_tf32(acc[mt][nt], afr[mt], bfr[nt]);
        }

        if (has_next) {
            storeS(buf ^ 1);
            __syncthreads();
            buf ^= 1;
        }
    }

#pragma unroll
    for (int nt = 0; nt < 4; nt++) {
        int c = n0 + nt * 8 + 2 * t;
        if (c < 64) {
#pragma unroll
            for (int mt = 0; mt < 4; mt++) {
                int r0 = brow + m0 + mt * 16 + g;
                if (r0 < N_NODES)
                    *(float2*)(g_t + (size_t)r0 * 64 + c) =
                        make_float2(acc[mt][nt][0], acc[mt][nt][1]);
                int r1 = r0 + 8;
                if (r1 < N_NODES)
                    *(float2*)(g_t + (size_t)r1 * 64 + c) =
                        make_float2(acc[mt][nt][2], acc[mt][nt][3]);
            }
        } else {
            int co = c - 64;
            float2 bb = *(const float2*)(b2 + co);
#pragma unroll
            for (int mt = 0; mt < 4; mt++) {
                int r0 = brow + m0 + mt * 16 + g;
                if (r0 < N_NODES)
                    *(float2*)(out + (size_t)r0 * 64 + co) =
                        make_float2(acc[mt][nt][0] + bb.x, acc[mt][nt][1] + bb.y);
                int r1 = r0 + 8;
                if (r1 < N_NODES)
                    *(float2*)(out + (size_t)r1 * 64 + co) =
                        make_float2(acc[mt][nt][2] + bb.x, acc[mt][nt][3] + bb.y);
            }
        }
    }
}

// ---------------------------------------------------------------------------
// Aggregation 2 + final (unchanged)
// ---------------------------------------------------------------------------
__global__ void k_agg2(float* __restrict__ out) {
    int node = blockIdx.x * (blockDim.x >> 5) + (threadIdx.x >> 5);
    int lane = threadIdx.x & 31;
    if (node >= N_NODES) return;

    int deg = min(g_cnt[node], CAP);
    const int* adj = g_adj + node * CAP;

    float2 a0 = make_float2(0.f, 0.f);
    float2 a1 = make_float2(0.f, 0.f);
    float2 a2 = make_float2(0.f, 0.f);
    float2 a3 = make_float2(0.f, 0.f);

    int p = 0;
    for (; p + 8 <= deg; p += 8) {
        int4 i0 = *(const int4*)(adj + p);
        int4 i1 = *(const int4*)(adj + p + 4);
        float2 v0 = ((const float2*)(g_t + (size_t)i0.x * OUT_C))[lane];
        float2 v1 = ((const float2*)(g_t + (size_t)i0.y * OUT_C))[lane];
        float2 v2 = ((const float2*)(g_t + (size_t)i0.z * OUT_C))[lane];
        float2 v3 = ((const float2*)(g_t + (size_t)i0.w * OUT_C))[lane];
        float2 v4 = ((const float2*)(g_t + (size_t)i1.x * OUT_C))[lane];
        float2 v5 = ((const float2*)(g_t + (size_t)i1.y * OUT_C))[lane];
        float2 v6 = ((const float2*)(g_t + (size_t)i1.z * OUT_C))[lane];
        float2 v7 = ((const float2*)(g_t + (size_t)i1.w * OUT_C))[lane];
        a0.x += v0.x; a0.y += v0.y;
        a1.x += v1.x; a1.y += v1.y;
        a2.x += v2.x; a2.y += v2.y;
        a3.x += v3.x; a3.y += v3.y;
        a0.x += v4.x; a0.y += v4.y;
        a1.x += v5.x; a1.y += v5.y;
        a2.x += v6.x; a2.y += v6.y;
        a3.x += v7.x; a3.y += v7.y;
    }
    if (p + 4 <= deg) {
        int4 i0 = *(const int4*)(adj + p);
        float2 v0 = ((const float2*)(g_t + (size_t)i0.x * OUT_C))[lane];
        float2 v1 = ((const float2*)(g_t + (size_t)i0.y * OUT_C))[lane];
        float2 v2 = ((const float2*)(g_t + (size_t)i0.z * OUT_C))[lane];
        float2 v3 = ((const float2*)(g_t + (size_t)i0.w * OUT_C))[lane];
        a0.x += v0.x; a0.y += v0.y;
        a1.x += v1.x; a1.y += v1.y;
        a2.x += v2.x; a2.y += v2.y;
        a3.x += v3.x; a3.y += v3.y;
        p += 4;
    }
    for (; p < deg; p++) {
        int s = adj[p];
        float2 v = ((const float2*)(g_t + (size_t)s * OUT_C))[lane];
        a0.x += v.x; a0.y += v.y;
    }
    float inv = (deg > 0) ? 1.f / (float)deg : 0.f;
    float sx = ((a0.x + a1.x) + (a2.x + a3.x)) * inv;
    float sy = ((a0.y + a1.y) + (a2.y + a3.y)) * inv;

    float2* o = (float2*)(out + (size_t)node * OUT_C) + lane;
    float2 cur = *o;
    cur.x += sx;
    cur.y += sy;
    *o = cur;
}

// ---------------------------------------------------------------------------
extern "C" void kernel_launch(void* const* d_in, const int* in_sizes, int n_in,
                              void* d_out, int out_size) {
    const float* x   = (const float*)d_in[0];
    const int*   ei  = (const int*)d_in[1];     // int32 (JAX default x64 off)
    const float* W1l = (const float*)d_in[2];
    const float* b1  = (const float*)d_in[3];
    const float* W1r = (const float*)d_in[4];
    const float* W2l = (const float*)d_in[5];
    const float* b2  = (const float*)d_in[6];
    const float* W2r = (const float*)d_in[7];
    float* out = (float*)d_out;

    const int E = in_sizes[1] / 2;

    k_zero<<<(N_NODES + 255) / 256, 256>>>();
    k_fill<<<(E + 255) / 256, 256>>>(ei, E);

    k_agg1<<<(N_NODES + 7) / 8, 256>>>(x);
    k_gemm1<<<(N_NODES + 127) / 128, 256>>>(x, W1l, b1, W1r);

    k_gemm2<<<(N_NODES + 127) / 128, 256>>>(W2l, b2, W2r, out);
    k_agg2<<<(N_NODES + 7) / 8, 256>>>(out);
}